// round 5
// baseline (speedup 1.0000x reference)
#include <cuda_runtime.h>
#include <math_constants.h>
#include <cstdint>

#define NN 50000
#define EE 400000
#define BB 16
#define SCAN_E 1024
#define SCAN_NB ((NN + SCAN_E - 1) / SCAN_E)  // 49
#define GM ((NN + 127) / 128)                 // 391 M-tiles

// ---------------- scratch (static device globals; no allocation) ----------------
__device__ float g_h0[NN * 64];
__device__ float g_h [NN * 64];
__device__ float g_fs[NN * 256];
__device__ float g_fd[NN * 256];
__device__ float g_cs[NN * 256];   // h0 @ W_src[64:] + b_src   (layer-invariant)
__device__ float g_cd[NN * 256];   // h0 @ W_dst[64:] + b_dst
__device__ int   g_rowptr[NN + 1];
__device__ int   g_cursor[NN];
__device__ int   g_counts[NN];
__device__ int   g_col[EE];
__device__ int   g_bsum[SCAN_NB];
__device__ int   g_boff[SCAN_NB];
__device__ float g_hg[BB * 64];

__device__ __forceinline__ uint32_t f2tf32(float f) {
    uint32_t r;
    asm("cvt.rna.tf32.f32 %0, %1;" : "=r"(r) : "f"(f));
    return r;
}

__device__ __forceinline__ void mma_tf32_16x8x8(float* d, uint32_t a0, uint32_t a1,
                                                uint32_t a2, uint32_t a3,
                                                uint32_t b0, uint32_t b1) {
    asm volatile(
        "mma.sync.aligned.m16n8k8.row.col.f32.tf32.tf32.f32 "
        "{%0,%1,%2,%3}, {%4,%5,%6,%7}, {%8,%9}, {%0,%1,%2,%3};"
        : "+f"(d[0]), "+f"(d[1]), "+f"(d[2]), "+f"(d[3])
        : "r"(a0), "r"(a1), "r"(a2), "r"(a3), "r"(b0), "r"(b1));
}

// ---------------- zero counters + graph accumulator ----------------
__global__ void k_zero() {
    int i = blockIdx.x * blockDim.x + threadIdx.x;
    if (i < NN) g_counts[i] = 0;
    if (i < BB * 64) g_hg[i] = 0.f;
}

// ---------------- h0 = feat @ W_in + b_in ----------------
__global__ void k_in(const float* __restrict__ feat, const float* __restrict__ Win,
                     const float* __restrict__ bin) {
    int idx = blockIdx.x * blockDim.x + threadIdx.x;
    if (idx >= NN * 64) return;
    int n = idx >> 6, d = idx & 63;
    float s = bin[d];
#pragma unroll
    for (int k = 0; k < 16; k++) s += feat[n * 16 + k] * Win[k * 64 + d];
    g_h0[idx] = s;
}

// ---------------- CSR build (keyed by dst) ----------------
__global__ void k_hist(const int* __restrict__ dst) {
    int e = blockIdx.x * blockDim.x + threadIdx.x;
    if (e < EE) atomicAdd(&g_counts[dst[e]], 1);
}

__global__ void k_scan1() {
    __shared__ int ws[8];
    int t = threadIdx.x, b = blockIdx.x;
    int base = b * SCAN_E + t * 4;
    int v0 = 0, v1 = 0, v2 = 0, v3 = 0;
    if (base + 0 < NN) v0 = g_counts[base + 0];
    if (base + 1 < NN) v1 = g_counts[base + 1];
    if (base + 2 < NN) v2 = g_counts[base + 2];
    if (base + 3 < NN) v3 = g_counts[base + 3];
    int s = v0 + v1 + v2 + v3;
    int lane = t & 31, wid = t >> 5;
    int x = s;
#pragma unroll
    for (int o = 1; o < 32; o <<= 1) {
        int u = __shfl_up_sync(0xffffffffu, x, o);
        if (lane >= o) x += u;
    }
    if (lane == 31) ws[wid] = x;
    __syncthreads();
    if (wid == 0 && lane < 8) {
        int w = ws[lane];
#pragma unroll
        for (int o = 1; o < 8; o <<= 1) {
            int u = __shfl_up_sync(0x000000ffu, w, o);
            if (lane >= o) w += u;
        }
        ws[lane] = w;
    }
    __syncthreads();
    int excl = (x - s) + (wid > 0 ? ws[wid - 1] : 0);
    int run = excl;
    if (base + 0 < NN) { g_rowptr[base + 0] = run; run += v0; }
    if (base + 1 < NN) { g_rowptr[base + 1] = run; run += v1; }
    if (base + 2 < NN) { g_rowptr[base + 2] = run; run += v2; }
    if (base + 3 < NN) { g_rowptr[base + 3] = run; run += v3; }
    if (t == blockDim.x - 1) g_bsum[b] = excl + s;
}

__global__ void k_scan2() {
    int t = threadIdx.x;
    __shared__ int w0tot;
    int v = (t < SCAN_NB) ? g_bsum[t] : 0;
    int lane = t & 31, wid = t >> 5;
    int x = v;
#pragma unroll
    for (int o = 1; o < 32; o <<= 1) {
        int u = __shfl_up_sync(0xffffffffu, x, o);
        if (lane >= o) x += u;
    }
    if (wid == 0 && lane == 31) w0tot = x;
    __syncthreads();
    int incl = x + (wid > 0 ? w0tot : 0);
    if (t < SCAN_NB) g_boff[t] = incl - v;
}

__global__ void k_scan3() {
    int t = threadIdx.x, b = blockIdx.x;
    int off = g_boff[b];
    int base = b * SCAN_E + t * 4;
#pragma unroll
    for (int i = 0; i < 4; i++) {
        int idx = base + i;
        if (idx < NN) {
            int r = g_rowptr[idx] + off;
            g_rowptr[idx] = r;
            g_cursor[idx] = r;
        }
    }
    if (b == 0 && t == 0) g_rowptr[NN] = EE;
}

__global__ void k_scatter(const int* __restrict__ src, const int* __restrict__ dst) {
    int e = blockIdx.x * blockDim.x + threadIdx.x;
    if (e < EE) {
        int pos = atomicAdd(&g_cursor[dst[e]], 1);
        g_col[pos] = src[e];
    }
}

// ---------------- tf32 mma.sync GEMM -------------------------------------------
// mode 0: Out(g_cs|g_cd) = g_h0 @ W[64:,:] + bias
// mode 1: Out(g_fs|g_fd) = g_h0 @ W[:64,:] + (g_cs|g_cd)
// mode 2: Out(g_fs|g_fd) = g_h  @ W[:64,:] + (g_cs|g_cd)
// CTA: 128(M) x 128(N), K=64 in 4 chunks of 16. 8 warps = 4(M) x 2(N), warp 32x64.
#define PAD 136
__global__ __launch_bounds__(256, 2)
void k_mma(int mode,
           const float* __restrict__ W_src, const float* __restrict__ W_dst,
           const float* __restrict__ bsrc, const float* __restrict__ bdst) {
    __shared__ uint32_t As[16 * PAD];
    __shared__ uint32_t Bs[16 * PAD];

    const float* A = (mode == 2) ? g_h : g_h0;
    int m0 = blockIdx.x * 128;
    int n0 = blockIdx.y * 128;
    int is_src = (n0 < 256);
    const float* Wb   = is_src ? W_src : W_dst;
    const float* W    = (mode == 0) ? (Wb + 64 * 256) : Wb;
    const float* Cm   = is_src ? g_cs : g_cd;
    const float* bias = is_src ? bsrc : bdst;
    float*       Out  = (mode == 0) ? (is_src ? g_cs : g_cd)
                                    : (is_src ? g_fs : g_fd);
    int cb = n0 & 255;

    int tid  = threadIdx.x;
    int lane = tid & 31, wid = tid >> 5;
    int wm = wid & 3, wn = wid >> 2;
    int lq = lane >> 2;   // 0..7
    int lr = lane & 3;    // 0..3

    float acc[2][8][4];
#pragma unroll
    for (int mi = 0; mi < 2; mi++)
#pragma unroll
        for (int nj = 0; nj < 8; nj++)
#pragma unroll
            for (int v = 0; v < 4; v++) acc[mi][nj][v] = 0.f;

    for (int kc = 0; kc < 64; kc += 16) {
        __syncthreads();
        // A chunk: 128 rows x 16 k -> As[k][m] transpose store
#pragma unroll
        for (int i = 0; i < 2; i++) {
            int t2 = tid * 2 + i;          // 0..511
            int m  = t2 >> 2;              // 0..127
            int kq = (t2 & 3) << 2;        // 0,4,8,12
            float4 v = make_float4(0.f, 0.f, 0.f, 0.f);
            int gm = m0 + m;
            if (gm < NN) v = *(const float4*)(A + gm * 64 + kc + kq);
            As[(kq + 0) * PAD + m] = f2tf32(v.x);
            As[(kq + 1) * PAD + m] = f2tf32(v.y);
            As[(kq + 2) * PAD + m] = f2tf32(v.z);
            As[(kq + 3) * PAD + m] = f2tf32(v.w);
        }
        // B chunk: Bs[k][n] = W[kc+k][cb+n], 16 x 128
#pragma unroll
        for (int i = 0; i < 2; i++) {
            int t2 = tid * 2 + i;
            int k  = t2 >> 5;              // 0..15
            int n4 = (t2 & 31) << 2;       // 0..124
            float4 w = *(const float4*)(W + (kc + k) * 256 + cb + n4);
            uint4 tw = make_uint4(f2tf32(w.x), f2tf32(w.y), f2tf32(w.z), f2tf32(w.w));
            *(uint4*)&Bs[k * PAD + n4] = tw;
        }
        __syncthreads();

#pragma unroll
        for (int ks = 0; ks < 16; ks += 8) {
            uint32_t bf[8][2];
#pragma unroll
            for (int nj = 0; nj < 8; nj++) {
                int nb = wn * 64 + nj * 8 + lq;
                bf[nj][0] = Bs[(ks + lr) * PAD + nb];
                bf[nj][1] = Bs[(ks + lr + 4) * PAD + nb];
            }
#pragma unroll
            for (int mi = 0; mi < 2; mi++) {
                int rb = wm * 32 + mi * 16 + lq;
                uint32_t a0 = As[(ks + lr) * PAD + rb];
                uint32_t a1 = As[(ks + lr) * PAD + rb + 8];
                uint32_t a2 = As[(ks + lr + 4) * PAD + rb];
                uint32_t a3 = As[(ks + lr + 4) * PAD + rb + 8];
#pragma unroll
                for (int nj = 0; nj < 8; nj++)
                    mma_tf32_16x8x8(acc[mi][nj], a0, a1, a2, a3, bf[nj][0], bf[nj][1]);
            }
        }
    }

    // epilogue: D fragment (16x8): c0,c1 at (row, col..col+1); c2,c3 at (row+8, col)
#pragma unroll
    for (int mi = 0; mi < 2; mi++) {
        int r0 = m0 + wm * 32 + mi * 16 + lq;
#pragma unroll
        for (int nj = 0; nj < 8; nj++) {
            int c = cb + wn * 64 + nj * 8 + lr * 2;
            if (mode == 0) {
                float2 bv = *(const float2*)(bias + c);
                if (r0 < NN) {
                    float2 o = make_float2(acc[mi][nj][0] + bv.x, acc[mi][nj][1] + bv.y);
                    *(float2*)(Out + (size_t)r0 * 256 + c) = o;
                }
                if (r0 + 8 < NN) {
                    float2 o = make_float2(acc[mi][nj][2] + bv.x, acc[mi][nj][3] + bv.y);
                    *(float2*)(Out + (size_t)(r0 + 8) * 256 + c) = o;
                }
            } else {
                if (r0 < NN) {
                    float2 cv = *(const float2*)(Cm + (size_t)r0 * 256 + c);
                    float2 o = make_float2(acc[mi][nj][0] + cv.x, acc[mi][nj][1] + cv.y);
                    *(float2*)(Out + (size_t)r0 * 256 + c) = o;
                }
                if (r0 + 8 < NN) {
                    float2 cv = *(const float2*)(Cm + (size_t)(r0 + 8) * 256 + c);
                    float2 o = make_float2(acc[mi][nj][2] + cv.x, acc[mi][nj][3] + cv.y);
                    *(float2*)(Out + (size_t)(r0 + 8) * 256 + c) = o;
                }
            }
        }
    }
}

// ---------------- edge stage: one warp per dst node, online softmax -------------
__global__ void k_edge(const float* __restrict__ attn) {
    int gw = (blockIdx.x * blockDim.x + threadIdx.x) >> 5;
    if (gw >= NN) return;
    int lane = threadIdx.x & 31;
    int base = lane << 3;

    int beg = g_rowptr[gw];
    int end = g_rowptr[gw + 1];

    float fdv[8], av[8], acc[8];
    {
        float4 v0 = *(const float4*)&g_fd[gw * 256 + base];
        float4 v1 = *(const float4*)&g_fd[gw * 256 + base + 4];
        fdv[0] = v0.x; fdv[1] = v0.y; fdv[2] = v0.z; fdv[3] = v0.w;
        fdv[4] = v1.x; fdv[5] = v1.y; fdv[6] = v1.z; fdv[7] = v1.w;
        float4 a0 = *(const float4*)&attn[base];
        float4 a1 = *(const float4*)&attn[base + 4];
        av[0] = a0.x; av[1] = a0.y; av[2] = a0.z; av[3] = a0.w;
        av[4] = a1.x; av[5] = a1.y; av[6] = a1.z; av[7] = a1.w;
    }
#pragma unroll
    for (int i = 0; i < 8; i++) acc[i] = 0.f;
    float m = -CUDART_INF_F, sden = 0.f;

    for (int e = beg; e < end; e++) {
        int j = g_col[e];
        const float* fp = g_fs + j * 256 + base;
        float4 f0 = *(const float4*)fp;
        float4 f1 = *(const float4*)(fp + 4);
        float fsv[8] = {f0.x, f0.y, f0.z, f0.w, f1.x, f1.y, f1.z, f1.w};

        float p = 0.f;
#pragma unroll
        for (int i = 0; i < 8; i++) {
            float x = fsv[i] + fdv[i];
            x = (x > 0.f) ? x : 0.2f * x;  // LeakyReLU(0.2)
            p += av[i] * x;
        }
        p += __shfl_xor_sync(0xffffffffu, p, 1);
        p += __shfl_xor_sync(0xffffffffu, p, 2);
        p += __shfl_xor_sync(0xffffffffu, p, 4);  // per-head logit

        float mn   = fmaxf(m, p);
        float cold = __expf(m - mn);
        float w    = __expf(p - mn);
        sden = sden * cold + w;
#pragma unroll
        for (int i = 0; i < 8; i++) acc[i] = acc[i] * cold + w * fsv[i];
        m = mn;
    }

    float inv = (end > beg) ? (1.f / sden) : 0.f;
    float out[8];
#pragma unroll
    for (int i = 0; i < 8; i++) {
        float r = tanhf(acc[i] * inv);
        r += __shfl_xor_sync(0xffffffffu, r, 8);
        r += __shfl_xor_sync(0xffffffffu, r, 16);  // sum over 4 heads
        out[i] = r;
    }
    if (lane < 8) {
        float4 o0 = make_float4(out[0], out[1], out[2], out[3]);
        float4 o1 = make_float4(out[4], out[5], out[6], out[7]);
        *(float4*)&g_h[gw * 64 + base]     = o0;
        *(float4*)&g_h[gw * 64 + base + 4] = o1;
    }
}

// ---------------- graph readout ----------------
__global__ void k_readout(const float* __restrict__ is_root, const int* __restrict__ gid) {
    __shared__ float sh[BB * 64];
    for (int i = threadIdx.x; i < BB * 64; i += blockDim.x) sh[i] = 0.f;
    __syncthreads();
    int npb = (NN + gridDim.x - 1) / gridDim.x;
    int n0 = blockIdx.x * npb;
    int n1 = min(n0 + npb, NN);
    int d = threadIdx.x & 63;
    for (int n = n0 + (threadIdx.x >> 6); n < n1; n += (blockDim.x >> 6)) {
        float v = g_h[n * 64 + d] * is_root[n];
        atomicAdd(&sh[gid[n] * 64 + d], v);
    }
    __syncthreads();
    for (int i = threadIdx.x; i < BB * 64; i += blockDim.x) atomicAdd(&g_hg[i], sh[i]);
}

// ---------------- out = hg @ W_out + b_out ----------------
__global__ void k_out(const float* __restrict__ Wout, const float* __restrict__ bout,
                      float* __restrict__ out) {
    int t = threadIdx.x;
    if (t >= BB * 32) return;
    int b = t >> 5, o = t & 31;
    float s = bout[o];
#pragma unroll
    for (int d = 0; d < 64; d++) s += g_hg[b * 64 + d] * Wout[d * 32 + o];
    out[t] = s;
}

// ---------------- launch ----------------
extern "C" void kernel_launch(void* const* d_in, const int* in_sizes, int n_in,
                              void* d_out, int out_size) {
    const float* feat    = (const float*)d_in[0];
    const float* is_root = (const float*)d_in[1];
    const int*   src     = (const int*)d_in[2];
    const int*   dst     = (const int*)d_in[3];
    const int*   gid     = (const int*)d_in[4];
    const float* W_in    = (const float*)d_in[5];
    const float* b_in    = (const float*)d_in[6];
    const float* W_src   = (const float*)d_in[7];
    const float* b_src   = (const float*)d_in[8];
    const float* W_dst   = (const float*)d_in[9];
    const float* b_dst   = (const float*)d_in[10];
    const float* attn    = (const float*)d_in[11];
    const float* W_out   = (const float*)d_in[12];
    const float* b_out   = (const float*)d_in[13];
    float* out = (float*)d_out;

    k_zero<<<(NN + 255) / 256, 256>>>();
    k_in<<<(NN * 64 + 255) / 256, 256>>>(feat, W_in, b_in);
    k_hist<<<(EE + 255) / 256, 256>>>(dst);
    k_scan1<<<SCAN_NB, 256>>>();
    k_scan2<<<1, 64>>>();
    k_scan3<<<SCAN_NB, 256>>>();
    k_scatter<<<(EE + 255) / 256, 256>>>(src, dst);

    dim3 tg(GM, 4);
    // precompute g_cs/g_cd = h0 @ W[64:,:] + b  (layer-invariant)
    k_mma<<<tg, 256>>>(0, W_src, W_dst, b_src, b_dst);

    for (int layer = 0; layer < 4; layer++) {
        k_mma<<<tg, 256>>>(layer == 0 ? 1 : 2, W_src, W_dst, b_src, b_dst);
        k_edge<<<(NN * 32 + 255) / 256, 256>>>(attn);
    }

    k_readout<<<512, 256>>>(is_root, gid);
    k_out<<<1, 512>>>(W_out, b_out, out);
}

// round 6
// speedup vs baseline: 1.2300x; 1.2300x over previous
#include <cuda_runtime.h>
#include <math_constants.h>
#include <cstdint>

#define NN 50000
#define EE 400000
#define BB 16
#define SCAN_E 1024
#define SCAN_NB ((NN + SCAN_E - 1) / SCAN_E)  // 49
#define GM ((NN + 127) / 128)                 // 391 M-tiles

// ---------------- scratch (static device globals; no allocation) ----------------
__device__ float g_h0[NN * 64];
__device__ float g_h [NN * 64];
__device__ float g_fs[NN * 256];
__device__ float g_fd[NN * 256];
__device__ float g_cs[NN * 256];   // h0 @ W_src[64:] + b_src   (layer-invariant)
__device__ float g_cd[NN * 256];   // h0 @ W_dst[64:] + b_dst
__device__ int   g_rowptr[NN + 1];
__device__ int   g_cursor[NN];
__device__ int   g_counts[NN];
__device__ int   g_col[EE];
__device__ int   g_bsum[SCAN_NB];
__device__ int   g_boff[SCAN_NB];
__device__ float g_hg[BB * 64];

// ---------------- packed f32x2 helpers ----------------
__device__ __forceinline__ void fma2(unsigned long long& d, unsigned long long a,
                                     unsigned long long b) {
    asm("fma.rn.f32x2 %0, %1, %2, %0;" : "+l"(d) : "l"(a), "l"(b));
}
__device__ __forceinline__ unsigned long long dup2(float v) {
    unsigned long long r;
    uint32_t u = __float_as_uint(v);
    asm("mov.b64 %0, {%1, %1};" : "=l"(r) : "r"(u));
    return r;
}
__device__ __forceinline__ void unpack2(unsigned long long v, float& lo, float& hi) {
    uint32_t l, h;
    asm("mov.b64 {%0, %1}, %2;" : "=r"(l), "=r"(h) : "l"(v));
    lo = __uint_as_float(l);
    hi = __uint_as_float(h);
}

// ---------------- zero counters + graph accumulator ----------------
__global__ void k_zero() {
    int i = blockIdx.x * blockDim.x + threadIdx.x;
    if (i < NN) g_counts[i] = 0;
    if (i < BB * 64) g_hg[i] = 0.f;
}

// ---------------- h0 = feat @ W_in + b_in ----------------
__global__ void k_in(const float* __restrict__ feat, const float* __restrict__ Win,
                     const float* __restrict__ bin) {
    int idx = blockIdx.x * blockDim.x + threadIdx.x;
    if (idx >= NN * 64) return;
    int n = idx >> 6, d = idx & 63;
    float s = bin[d];
#pragma unroll
    for (int k = 0; k < 16; k++) s += feat[n * 16 + k] * Win[k * 64 + d];
    g_h0[idx] = s;
}

// ---------------- CSR build (keyed by dst) ----------------
__global__ void k_hist(const int* __restrict__ dst) {
    int e = blockIdx.x * blockDim.x + threadIdx.x;
    if (e < EE) atomicAdd(&g_counts[dst[e]], 1);
}

__global__ void k_scan1() {
    __shared__ int ws[8];
    int t = threadIdx.x, b = blockIdx.x;
    int base = b * SCAN_E + t * 4;
    int v0 = 0, v1 = 0, v2 = 0, v3 = 0;
    if (base + 0 < NN) v0 = g_counts[base + 0];
    if (base + 1 < NN) v1 = g_counts[base + 1];
    if (base + 2 < NN) v2 = g_counts[base + 2];
    if (base + 3 < NN) v3 = g_counts[base + 3];
    int s = v0 + v1 + v2 + v3;
    int lane = t & 31, wid = t >> 5;
    int x = s;
#pragma unroll
    for (int o = 1; o < 32; o <<= 1) {
        int u = __shfl_up_sync(0xffffffffu, x, o);
        if (lane >= o) x += u;
    }
    if (lane == 31) ws[wid] = x;
    __syncthreads();
    if (wid == 0 && lane < 8) {
        int w = ws[lane];
#pragma unroll
        for (int o = 1; o < 8; o <<= 1) {
            int u = __shfl_up_sync(0x000000ffu, w, o);
            if (lane >= o) w += u;
        }
        ws[lane] = w;
    }
    __syncthreads();
    int excl = (x - s) + (wid > 0 ? ws[wid - 1] : 0);
    int run = excl;
    if (base + 0 < NN) { g_rowptr[base + 0] = run; run += v0; }
    if (base + 1 < NN) { g_rowptr[base + 1] = run; run += v1; }
    if (base + 2 < NN) { g_rowptr[base + 2] = run; run += v2; }
    if (base + 3 < NN) { g_rowptr[base + 3] = run; run += v3; }
    if (t == blockDim.x - 1) g_bsum[b] = excl + s;
}

__global__ void k_scan2() {
    int t = threadIdx.x;
    __shared__ int w0tot;
    int v = (t < SCAN_NB) ? g_bsum[t] : 0;
    int lane = t & 31, wid = t >> 5;
    int x = v;
#pragma unroll
    for (int o = 1; o < 32; o <<= 1) {
        int u = __shfl_up_sync(0xffffffffu, x, o);
        if (lane >= o) x += u;
    }
    if (wid == 0 && lane == 31) w0tot = x;
    __syncthreads();
    int incl = x + (wid > 0 ? w0tot : 0);
    if (t < SCAN_NB) g_boff[t] = incl - v;
}

__global__ void k_scan3() {
    int t = threadIdx.x, b = blockIdx.x;
    int off = g_boff[b];
    int base = b * SCAN_E + t * 4;
#pragma unroll
    for (int i = 0; i < 4; i++) {
        int idx = base + i;
        if (idx < NN) {
            int r = g_rowptr[idx] + off;
            g_rowptr[idx] = r;
            g_cursor[idx] = r;
        }
    }
    if (b == 0 && t == 0) g_rowptr[NN] = EE;
}

__global__ void k_scatter(const int* __restrict__ src, const int* __restrict__ dst) {
    int e = blockIdx.x * blockDim.x + threadIdx.x;
    if (e < EE) {
        int pos = atomicAdd(&g_cursor[dst[e]], 1);
        g_col[pos] = src[e];
    }
}

// ---------------- K=64 GEMM, fma.rn.f32x2 microkernel --------------------------
// mode 0: Out(g_cs|g_cd) = g_h0 @ W[64:,:] + bias
// mode 1: Out(g_fs|g_fd) = g_h0 @ W[:64,:] + (g_cs|g_cd)
// mode 2: Out(g_fs|g_fd) = g_h  @ W[:64,:] + (g_cs|g_cd)
__global__ __launch_bounds__(256, 2)
void k_gemm64(int mode,
              const float* __restrict__ W_src, const float* __restrict__ W_dst,
              const float* __restrict__ bsrc, const float* __restrict__ bdst) {
    __shared__ float As[8][128];
    __shared__ float Bs[8][128];

    const float* A = (mode == 2) ? g_h : g_h0;

    int m0 = blockIdx.x * 128;
    int n0 = blockIdx.y * 128;
    int is_src = (n0 < 256);
    const float* Wb   = is_src ? W_src : W_dst;
    const float* W    = (mode == 0) ? (Wb + 64 * 256) : Wb;
    const float* Cm   = is_src ? g_cs : g_cd;
    const float* bias = is_src ? bsrc : bdst;
    float*       Out  = (mode == 0) ? (is_src ? g_cs : g_cd)
                                    : (is_src ? g_fs : g_fd);
    int cb = n0 & 255;

    int t  = threadIdx.x;
    int tx = t & 15, ty = t >> 4;

    int arow = t >> 1;
    int ako  = (t & 1) << 2;
    int grow = m0 + arow;
    int bk = t >> 5;
    int bc = (t & 31) << 2;

    // acc2[i2][j]: lo = row ty*8+2*i2, hi = row ty*8+2*i2+1, col tx*8+j
    unsigned long long acc2[4][8];
#pragma unroll
    for (int i2 = 0; i2 < 4; i2++)
#pragma unroll
        for (int j = 0; j < 8; j++) acc2[i2][j] = 0ULL;

    // preload chunk 0
    float4 av = make_float4(0.f, 0.f, 0.f, 0.f);
    if (grow < NN) av = *(const float4*)(A + grow * 64 + ako);
    float4 bv = *(const float4*)(W + bk * 256 + cb + bc);

    for (int kc = 0; kc < 64; kc += 8) {
        As[ako + 0][arow] = av.x;
        As[ako + 1][arow] = av.y;
        As[ako + 2][arow] = av.z;
        As[ako + 3][arow] = av.w;
        *(float4*)&Bs[bk][bc] = bv;
        __syncthreads();
        if (kc < 56) {  // prefetch next chunk, overlaps with compute below
            int kn = kc + 8;
            av = make_float4(0.f, 0.f, 0.f, 0.f);
            if (grow < NN) av = *(const float4*)(A + grow * 64 + kn + ako);
            bv = *(const float4*)(W + (kn + bk) * 256 + cb + bc);
        }
#pragma unroll
        for (int k2 = 0; k2 < 8; k2++) {
            const ulonglong2 a01 = *(const ulonglong2*)&As[k2][ty * 8];
            const ulonglong2 a23 = *(const ulonglong2*)&As[k2][ty * 8 + 4];
            unsigned long long a2[4] = {a01.x, a01.y, a23.x, a23.y};
            float4 b0 = *(const float4*)&Bs[k2][tx * 8];
            float4 b1 = *(const float4*)&Bs[k2][tx * 8 + 4];
            unsigned long long bd[8];
            bd[0] = dup2(b0.x); bd[1] = dup2(b0.y); bd[2] = dup2(b0.z); bd[3] = dup2(b0.w);
            bd[4] = dup2(b1.x); bd[5] = dup2(b1.y); bd[6] = dup2(b1.z); bd[7] = dup2(b1.w);
#pragma unroll
            for (int i2 = 0; i2 < 4; i2++)
#pragma unroll
                for (int j = 0; j < 8; j++) fma2(acc2[i2][j], a2[i2], bd[j]);
        }
        __syncthreads();
    }

    // epilogue
    float bb[8];
    if (mode == 0) {
#pragma unroll
        for (int j = 0; j < 8; j++) bb[j] = bias[cb + tx * 8 + j];
    }
#pragma unroll
    for (int i2 = 0; i2 < 4; i2++) {
        float lo[8], hi[8];
#pragma unroll
        for (int j = 0; j < 8; j++) unpack2(acc2[i2][j], lo[j], hi[j]);
        int r_lo = m0 + ty * 8 + 2 * i2;
        int r_hi = r_lo + 1;
        if (mode == 0) {
            if (r_lo < NN) {
                float4 o0 = make_float4(lo[0] + bb[0], lo[1] + bb[1], lo[2] + bb[2], lo[3] + bb[3]);
                float4 o1 = make_float4(lo[4] + bb[4], lo[5] + bb[5], lo[6] + bb[6], lo[7] + bb[7]);
                *(float4*)&Out[(size_t)r_lo * 256 + cb + tx * 8]     = o0;
                *(float4*)&Out[(size_t)r_lo * 256 + cb + tx * 8 + 4] = o1;
            }
            if (r_hi < NN) {
                float4 o0 = make_float4(hi[0] + bb[0], hi[1] + bb[1], hi[2] + bb[2], hi[3] + bb[3]);
                float4 o1 = make_float4(hi[4] + bb[4], hi[5] + bb[5], hi[6] + bb[6], hi[7] + bb[7]);
                *(float4*)&Out[(size_t)r_hi * 256 + cb + tx * 8]     = o0;
                *(float4*)&Out[(size_t)r_hi * 256 + cb + tx * 8 + 4] = o1;
            }
        } else {
            if (r_lo < NN) {
                const float* Cp = Cm + (size_t)r_lo * 256 + cb + tx * 8;
                float4 c0 = *(const float4*)Cp;
                float4 c1 = *(const float4*)(Cp + 4);
                float4 o0 = make_float4(lo[0] + c0.x, lo[1] + c0.y, lo[2] + c0.z, lo[3] + c0.w);
                float4 o1 = make_float4(lo[4] + c1.x, lo[5] + c1.y, lo[6] + c1.z, lo[7] + c1.w);
                *(float4*)&Out[(size_t)r_lo * 256 + cb + tx * 8]     = o0;
                *(float4*)&Out[(size_t)r_lo * 256 + cb + tx * 8 + 4] = o1;
            }
            if (r_hi < NN) {
                const float* Cp = Cm + (size_t)r_hi * 256 + cb + tx * 8;
                float4 c0 = *(const float4*)Cp;
                float4 c1 = *(const float4*)(Cp + 4);
                float4 o0 = make_float4(hi[0] + c0.x, hi[1] + c0.y, hi[2] + c0.z, hi[3] + c0.w);
                float4 o1 = make_float4(hi[4] + c1.x, hi[5] + c1.y, hi[6] + c1.z, hi[7] + c1.w);
                *(float4*)&Out[(size_t)r_hi * 256 + cb + tx * 8]     = o0;
                *(float4*)&Out[(size_t)r_hi * 256 + cb + tx * 8 + 4] = o1;
            }
        }
    }
}

// ---------------- edge stage: warp/node, 4-edge batched online softmax ----------
__global__ void k_edge(const float* __restrict__ attn) {
    int gw = (blockIdx.x * blockDim.x + threadIdx.x) >> 5;
    if (gw >= NN) return;
    int lane = threadIdx.x & 31;
    int base = lane << 3;

    int beg = g_rowptr[gw];
    int end = g_rowptr[gw + 1];

    float fdv[8], av[8], acc[8];
    {
        float4 v0 = *(const float4*)&g_fd[gw * 256 + base];
        float4 v1 = *(const float4*)&g_fd[gw * 256 + base + 4];
        fdv[0] = v0.x; fdv[1] = v0.y; fdv[2] = v0.z; fdv[3] = v0.w;
        fdv[4] = v1.x; fdv[5] = v1.y; fdv[6] = v1.z; fdv[7] = v1.w;
        float4 a0 = *(const float4*)&attn[base];
        float4 a1 = *(const float4*)&attn[base + 4];
        av[0] = a0.x; av[1] = a0.y; av[2] = a0.z; av[3] = a0.w;
        av[4] = a1.x; av[5] = a1.y; av[6] = a1.z; av[7] = a1.w;
    }
#pragma unroll
    for (int i = 0; i < 8; i++) acc[i] = 0.f;
    float m = -CUDART_INF_F, sden = 0.f;

    int e = beg;
    for (; e + 4 <= end; e += 4) {
        int j0 = g_col[e + 0], j1 = g_col[e + 1], j2 = g_col[e + 2], j3 = g_col[e + 3];
        float4 x00 = *(const float4*)(g_fs + (size_t)j0 * 256 + base);
        float4 x01 = *(const float4*)(g_fs + (size_t)j0 * 256 + base + 4);
        float4 x10 = *(const float4*)(g_fs + (size_t)j1 * 256 + base);
        float4 x11 = *(const float4*)(g_fs + (size_t)j1 * 256 + base + 4);
        float4 x20 = *(const float4*)(g_fs + (size_t)j2 * 256 + base);
        float4 x21 = *(const float4*)(g_fs + (size_t)j2 * 256 + base + 4);
        float4 x30 = *(const float4*)(g_fs + (size_t)j3 * 256 + base);
        float4 x31 = *(const float4*)(g_fs + (size_t)j3 * 256 + base + 4);
        float f0[8] = {x00.x, x00.y, x00.z, x00.w, x01.x, x01.y, x01.z, x01.w};
        float f1[8] = {x10.x, x10.y, x10.z, x10.w, x11.x, x11.y, x11.z, x11.w};
        float f2[8] = {x20.x, x20.y, x20.z, x20.w, x21.x, x21.y, x21.z, x21.w};
        float f3[8] = {x30.x, x30.y, x30.z, x30.w, x31.x, x31.y, x31.z, x31.w};

        float p0 = 0.f, p1 = 0.f, p2 = 0.f, p3 = 0.f;
#pragma unroll
        for (int i = 0; i < 8; i++) {
            float y0 = f0[i] + fdv[i]; y0 = (y0 > 0.f) ? y0 : 0.2f * y0;
            float y1 = f1[i] + fdv[i]; y1 = (y1 > 0.f) ? y1 : 0.2f * y1;
            float y2 = f2[i] + fdv[i]; y2 = (y2 > 0.f) ? y2 : 0.2f * y2;
            float y3 = f3[i] + fdv[i]; y3 = (y3 > 0.f) ? y3 : 0.2f * y3;
            p0 += av[i] * y0; p1 += av[i] * y1; p2 += av[i] * y2; p3 += av[i] * y3;
        }
        p0 += __shfl_xor_sync(0xffffffffu, p0, 1);
        p1 += __shfl_xor_sync(0xffffffffu, p1, 1);
        p2 += __shfl_xor_sync(0xffffffffu, p2, 1);
        p3 += __shfl_xor_sync(0xffffffffu, p3, 1);
        p0 += __shfl_xor_sync(0xffffffffu, p0, 2);
        p1 += __shfl_xor_sync(0xffffffffu, p1, 2);
        p2 += __shfl_xor_sync(0xffffffffu, p2, 2);
        p3 += __shfl_xor_sync(0xffffffffu, p3, 2);
        p0 += __shfl_xor_sync(0xffffffffu, p0, 4);
        p1 += __shfl_xor_sync(0xffffffffu, p1, 4);
        p2 += __shfl_xor_sync(0xffffffffu, p2, 4);
        p3 += __shfl_xor_sync(0xffffffffu, p3, 4);

        float mn = fmaxf(fmaxf(m, fmaxf(p0, p1)), fmaxf(p2, p3));
        float cold = __expf(m - mn);
        float w0 = __expf(p0 - mn);
        float w1 = __expf(p1 - mn);
        float w2 = __expf(p2 - mn);
        float w3 = __expf(p3 - mn);
        sden = sden * cold + ((w0 + w1) + (w2 + w3));
#pragma unroll
        for (int i = 0; i < 8; i++) {
            float s = acc[i] * cold;
            s += w0 * f0[i];
            s += w1 * f1[i];
            s += w2 * f2[i];
            s += w3 * f3[i];
            acc[i] = s;
        }
        m = mn;
    }
    for (; e < end; e++) {
        int j = g_col[e];
        float4 y0 = *(const float4*)(g_fs + (size_t)j * 256 + base);
        float4 y1 = *(const float4*)(g_fs + (size_t)j * 256 + base + 4);
        float fv[8] = {y0.x, y0.y, y0.z, y0.w, y1.x, y1.y, y1.z, y1.w};
        float p = 0.f;
#pragma unroll
        for (int i = 0; i < 8; i++) {
            float x = fv[i] + fdv[i];
            x = (x > 0.f) ? x : 0.2f * x;
            p += av[i] * x;
        }
        p += __shfl_xor_sync(0xffffffffu, p, 1);
        p += __shfl_xor_sync(0xffffffffu, p, 2);
        p += __shfl_xor_sync(0xffffffffu, p, 4);
        float mn = fmaxf(m, p);
        float cold = __expf(m - mn);
        float w = __expf(p - mn);
        sden = sden * cold + w;
#pragma unroll
        for (int i = 0; i < 8; i++) acc[i] = acc[i] * cold + w * fv[i];
        m = mn;
    }

    float inv = (end > beg) ? (1.f / sden) : 0.f;
    float out[8];
#pragma unroll
    for (int i = 0; i < 8; i++) {
        float r = tanhf(acc[i] * inv);
        r += __shfl_xor_sync(0xffffffffu, r, 8);
        r += __shfl_xor_sync(0xffffffffu, r, 16);  // sum over 4 heads
        out[i] = r;
    }
    if (lane < 8) {
        float4 o0 = make_float4(out[0], out[1], out[2], out[3]);
        float4 o1 = make_float4(out[4], out[5], out[6], out[7]);
        *(float4*)&g_h[gw * 64 + base]     = o0;
        *(float4*)&g_h[gw * 64 + base + 4] = o1;
    }
}

// ---------------- graph readout ----------------
__global__ void k_readout(const float* __restrict__ is_root, const int* __restrict__ gid) {
    __shared__ float sh[BB * 64];
    for (int i = threadIdx.x; i < BB * 64; i += blockDim.x) sh[i] = 0.f;
    __syncthreads();
    int npb = (NN + gridDim.x - 1) / gridDim.x;
    int n0 = blockIdx.x * npb;
    int n1 = min(n0 + npb, NN);
    int d = threadIdx.x & 63;
    for (int n = n0 + (threadIdx.x >> 6); n < n1; n += (blockDim.x >> 6)) {
        float v = g_h[n * 64 + d] * is_root[n];
        atomicAdd(&sh[gid[n] * 64 + d], v);
    }
    __syncthreads();
    for (int i = threadIdx.x; i < BB * 64; i += blockDim.x) atomicAdd(&g_hg[i], sh[i]);
}

// ---------------- out = hg @ W_out + b_out ----------------
__global__ void k_out(const float* __restrict__ Wout, const float* __restrict__ bout,
                      float* __restrict__ out) {
    int t = threadIdx.x;
    if (t >= BB * 32) return;
    int b = t >> 5, o = t & 31;
    float s = bout[o];
#pragma unroll
    for (int d = 0; d < 64; d++) s += g_hg[b * 64 + d] * Wout[d * 32 + o];
    out[t] = s;
}

// ---------------- launch ----------------
extern "C" void kernel_launch(void* const* d_in, const int* in_sizes, int n_in,
                              void* d_out, int out_size) {
    const float* feat    = (const float*)d_in[0];
    const float* is_root = (const float*)d_in[1];
    const int*   src     = (const int*)d_in[2];
    const int*   dst     = (const int*)d_in[3];
    const int*   gid     = (const int*)d_in[4];
    const float* W_in    = (const float*)d_in[5];
    const float* b_in    = (const float*)d_in[6];
    const float* W_src   = (const float*)d_in[7];
    const float* b_src   = (const float*)d_in[8];
    const float* W_dst   = (const float*)d_in[9];
    const float* b_dst   = (const float*)d_in[10];
    const float* attn    = (const float*)d_in[11];
    const float* W_out   = (const float*)d_in[12];
    const float* b_out   = (const float*)d_in[13];
    float* out = (float*)d_out;

    k_zero<<<(NN + 255) / 256, 256>>>();
    k_in<<<(NN * 64 + 255) / 256, 256>>>(feat, W_in, b_in);
    k_hist<<<(EE + 255) / 256, 256>>>(dst);
    k_scan1<<<SCAN_NB, 256>>>();
    k_scan2<<<1, 64>>>();
    k_scan3<<<SCAN_NB, 256>>>();
    k_scatter<<<(EE + 255) / 256, 256>>>(src, dst);

    dim3 ggrid(GM, 4);
    // precompute g_cs/g_cd = h0 @ W[64:,:] + b  (layer-invariant)
    k_gemm64<<<ggrid, 256>>>(0, W_src, W_dst, b_src, b_dst);

    for (int layer = 0; layer < 4; layer++) {
        k_gemm64<<<ggrid, 256>>>(layer == 0 ? 1 : 2, W_src, W_dst, b_src, b_dst);
        k_edge<<<(NN * 32 + 255) / 256, 256>>>(attn);
    }

    k_readout<<<512, 256>>>(is_root, gid);
    k_out<<<1, 512>>>(W_out, b_out, out);
}